// round 3
// baseline (speedup 1.0000x reference)
#include <cuda_runtime.h>
#include <cstdint>

#define HIDDEN   256
#define NHL      4
#define MTILE    64
#define KS       16
#define NSLAB    16         // HIDDEN / KS
#define THREADS  256
#define NSLABS_TOTAL (NHL * NSLAB)

// smem (floats): xa[64*256] wbuf[2*16*256] omg[64] cs[256] wfs[256]  ~= 98.25 KB
#define SMEM_FLOATS (MTILE*HIDDEN + 2*KS*HIDDEN + MTILE + MTILE*4 + HIDDEN)

__device__ __forceinline__ void cp_async16(float* dst, const float4* src) {
    uint32_t s = (uint32_t)__cvta_generic_to_shared(dst);
    asm volatile("cp.async.cg.shared.global [%0], [%1], 16;\n" :: "r"(s), "l"(src));
}
__device__ __forceinline__ void cp_commit() { asm volatile("cp.async.commit_group;\n" ::); }
template<int W> __device__ __forceinline__ void cp_wait() {
    asm volatile("cp.async.wait_group %0;\n" :: "n"(W));
}

// ---- packed fp32x2 (FFMA2) helpers ----
__device__ __forceinline__ void fma2(uint64_t& d, uint64_t a, uint64_t b) {
    asm volatile("fma.rn.f32x2 %0, %1, %2, %0;" : "+l"(d) : "l"(a), "l"(b));
}
__device__ __forceinline__ uint64_t dup2(float x) {
    uint64_t d; asm("mov.b64 %0, {%1, %1};" : "=l"(d) : "f"(x)); return d;
}
__device__ __forceinline__ void unpack2(float& lo, float& hi, uint64_t v) {
    asm("mov.b64 {%0, %1}, %2;" : "=f"(lo), "=f"(hi) : "l"(v));
}

// sin with Cody-Waite range reduction; abs err ~3e-7
__device__ __forceinline__ float fast_sin(float x) {
    float n = rintf(x * 0.15915494309189535f);
    float r = fmaf(n, -6.2831854820251465f, x);
    r = fmaf(n, 1.7484555e-7f, r);
    return __sinf(r);
}

__device__ __forceinline__ float4 ldg4(const float* p) {
    return __ldg(reinterpret_cast<const float4*>(p));
}

// stream weight slab g (64 slabs of 16x256) into wbuf[g&1]
__device__ __forceinline__ void issue_slab(const float* __restrict__ wh,
                                           float* wbuf, int g, int tid) {
    const float4* src = reinterpret_cast<const float4*>(wh + (size_t)g * KS * HIDDEN) + tid;
    float* dst = wbuf + (g & 1) * (KS * HIDDEN) + tid * 4;
    #pragma unroll
    for (int r = 0; r < (KS * HIDDEN / 4) / THREADS; r++)   // 4 x 16B per thread
        cp_async16(dst + r * THREADS * 4, src + r * THREADS);
    cp_commit();
}

__global__ void __launch_bounds__(THREADS, 2)
siren_fused_kernel(const float* __restrict__ coords,
                   const float* __restrict__ ow1, const float* __restrict__ ob1,
                   const float* __restrict__ ow2, const float* __restrict__ ob2,
                   const float* __restrict__ w0,  const float* __restrict__ b0,
                   const float* __restrict__ wh,  const float* __restrict__ bh,
                   const float* __restrict__ wf,  const float* __restrict__ bf,
                   float* __restrict__ out)
{
    extern __shared__ float smem[];
    float* xa   = smem;                       // [64][256] single buffer (per-warp rows)
    float* wbuf = xa + MTILE * HIDDEN;        // [2][KS*HIDDEN]
    float* omg  = wbuf + 2 * KS * HIDDEN;     // [64]
    float* cs   = omg + MTILE;                // [64][4]
    float* wfs  = cs + MTILE * 4;             // [256]

    const int tid = threadIdx.x;
    const int mt  = tid >> 5;                 // warp id -> m tile (owns rows m0..m0+7)
    const int nt  = tid & 31;
    const int m0  = mt * 8;
    const int cA  = nt * 4;
    const int cB  = 128 + nt * 4;
    const long base = (long)blockIdx.x * MTILE;

    issue_slab(wh, wbuf, 0, tid);

    cs[tid]  = coords[base * 4 + tid];
    wfs[tid] = wf[tid];
    __syncthreads();

    // ---- omega predictor (threads 0..63) ----
    if (tid < MTILE) {
        float c0 = cs[tid * 4 + 0], c1 = cs[tid * 4 + 1];
        float c2 = cs[tid * 4 + 2], c3 = cs[tid * 4 + 3];
        float s = __ldg(ob2);
        #pragma unroll 4
        for (int j = 0; j < 64; j++) {
            float h = __ldg(&ow1[j]) * c0;
            h = fmaf(__ldg(&ow1[64  + j]), c1, h);
            h = fmaf(__ldg(&ow1[128 + j]), c2, h);
            h = fmaf(__ldg(&ow1[192 + j]), c3, h);
            h += __ldg(&ob1[j]);
            h = fmaxf(h, 0.0f);
            s = fmaf(h, __ldg(&ow2[j]), s);
        }
        float sig = 1.0f / (1.0f + __expf(-s));
        omg[tid] = 10.0f + 90.0f * sig;
    }
    __syncthreads();

    // ---- SIREN layer 0: x = sin(omega * (coords @ w0 + b0)), K=4 ----
    {
        float accA[8][4], accB[8][4];
        #pragma unroll
        for (int i = 0; i < 8; i++)
            #pragma unroll
            for (int j = 0; j < 4; j++) { accA[i][j] = 0.0f; accB[i][j] = 0.0f; }
        #pragma unroll
        for (int k = 0; k < 4; k++) {
            float4 bA = ldg4(&w0[k * HIDDEN + cA]);
            float4 bB = ldg4(&w0[k * HIDDEN + cB]);
            #pragma unroll
            for (int i = 0; i < 8; i++) {
                float a = cs[(m0 + i) * 4 + k];
                accA[i][0] = fmaf(a, bA.x, accA[i][0]);
                accA[i][1] = fmaf(a, bA.y, accA[i][1]);
                accA[i][2] = fmaf(a, bA.z, accA[i][2]);
                accA[i][3] = fmaf(a, bA.w, accA[i][3]);
                accB[i][0] = fmaf(a, bB.x, accB[i][0]);
                accB[i][1] = fmaf(a, bB.y, accB[i][1]);
                accB[i][2] = fmaf(a, bB.z, accB[i][2]);
                accB[i][3] = fmaf(a, bB.w, accB[i][3]);
            }
        }
        float4 biA = ldg4(&b0[cA]);
        float4 biB = ldg4(&b0[cB]);
        #pragma unroll
        for (int i = 0; i < 8; i++) {
            float om = omg[m0 + i];
            float4 vA, vB;
            vA.x = fast_sin(om * (accA[i][0] + biA.x));
            vA.y = fast_sin(om * (accA[i][1] + biA.y));
            vA.z = fast_sin(om * (accA[i][2] + biA.z));
            vA.w = fast_sin(om * (accA[i][3] + biA.w));
            vB.x = fast_sin(om * (accB[i][0] + biB.x));
            vB.y = fast_sin(om * (accB[i][1] + biB.y));
            vB.z = fast_sin(om * (accB[i][2] + biB.z));
            vB.w = fast_sin(om * (accB[i][3] + biB.w));
            *reinterpret_cast<float4*>(&xa[(m0 + i) * HIDDEN + cA]) = vA;
            *reinterpret_cast<float4*>(&xa[(m0 + i) * HIDDEN + cB]) = vB;
        }
    }
    __syncwarp();   // xa rows are per-warp private; CTA sync not needed for xa

    // ---- 4 hidden layers, in-place update of xa, FFMA2 mainloop ----
    #pragma unroll 1
    for (int l = 0; l < NHL; l++) {
        uint64_t accA[8][2], accB[8][2];
        #pragma unroll
        for (int i = 0; i < 8; i++) {
            accA[i][0] = 0ull; accA[i][1] = 0ull;
            accB[i][0] = 0ull; accB[i][1] = 0ull;
        }

        #pragma unroll 1
        for (int s = 0; s < NSLAB; s++) {
            int g = l * NSLAB + s;
            // buffer (g+1)&1 was freed by the sync at the end of the previous slab
            if (g + 1 < NSLABS_TOTAL) {
                issue_slab(wh, wbuf, g + 1, tid);
                cp_wait<1>();
            } else {
                cp_wait<0>();
            }
            __syncthreads();   // slab g visible to all warps
            const float* wb = wbuf + (g & 1) * (KS * HIDDEN);
            const float* xk = &xa[m0 * HIDDEN + s * KS];

            #pragma unroll 2
            for (int kp = 0; kp < KS / 2; kp++) {
                float2 a[8];
                #pragma unroll
                for (int i = 0; i < 8; i++)
                    a[i] = *reinterpret_cast<const float2*>(xk + i * HIDDEN + kp * 2);
                #pragma unroll
                for (int kk = 0; kk < 2; kk++) {
                    ulonglong2 bA = *reinterpret_cast<const ulonglong2*>(&wb[(kp * 2 + kk) * HIDDEN + cA]);
                    ulonglong2 bB = *reinterpret_cast<const ulonglong2*>(&wb[(kp * 2 + kk) * HIDDEN + cB]);
                    #pragma unroll
                    for (int i = 0; i < 8; i++) {
                        uint64_t ad = dup2(kk ? a[i].y : a[i].x);
                        fma2(accA[i][0], ad, bA.x);
                        fma2(accA[i][1], ad, bA.y);
                        fma2(accB[i][0], ad, bB.x);
                        fma2(accB[i][1], ad, bB.y);
                    }
                }
            }
            __syncthreads();   // all warps done with buffer g&1 (next iter refills it)
        }

        float4 bhA = ldg4(&bh[l * HIDDEN + cA]);
        float4 bhB = ldg4(&bh[l * HIDDEN + cB]);
        __syncwarp();          // all lanes finished reading warp's rows before overwrite
        #pragma unroll
        for (int i = 0; i < 8; i++) {
            float om = omg[m0 + i];
            float a0, a1, a2, a3, b0v, b1v, b2v, b3v;
            unpack2(a0, a1, accA[i][0]);
            unpack2(a2, a3, accA[i][1]);
            unpack2(b0v, b1v, accB[i][0]);
            unpack2(b2v, b3v, accB[i][1]);
            float4 vA, vB;
            vA.x = fast_sin(om * (a0 + bhA.x));
            vA.y = fast_sin(om * (a1 + bhA.y));
            vA.z = fast_sin(om * (a2 + bhA.z));
            vA.w = fast_sin(om * (a3 + bhA.w));
            vB.x = fast_sin(om * (b0v + bhB.x));
            vB.y = fast_sin(om * (b1v + bhB.y));
            vB.z = fast_sin(om * (b2v + bhB.z));
            vB.w = fast_sin(om * (b3v + bhB.w));
            *reinterpret_cast<float4*>(&xa[(m0 + i) * HIDDEN + cA]) = vA;
            *reinterpret_cast<float4*>(&xa[(m0 + i) * HIDDEN + cB]) = vB;
        }
        __syncwarp();          // writes visible to this warp's lanes before next reads
    }

    // ---- head: out[m] = x[m] @ wf + bf (one warp per 8 points) ----
    {
        const int w = tid >> 5, lane = tid & 31;
        const float bfv = __ldg(bf);
        const float4* wr = reinterpret_cast<const float4*>(&wfs[lane * 8]);
        float4 w1 = wr[0], w2 = wr[1];
        #pragma unroll
        for (int p = 0; p < 8; p++) {
            int m = w * 8 + p;
            const float4* xr = reinterpret_cast<const float4*>(&xa[m * HIDDEN + lane * 8]);
            float4 x1 = xr[0], x2 = xr[1];
            float par = x1.x * w1.x + x1.y * w1.y + x1.z * w1.z + x1.w * w1.w
                      + x2.x * w2.x + x2.y * w2.y + x2.z * w2.z + x2.w * w2.w;
            #pragma unroll
            for (int off = 16; off > 0; off >>= 1)
                par += __shfl_xor_sync(0xffffffff, par, off);
            if (lane == 0) out[base + m] = par + bfv;
        }
    }
}

extern "C" void kernel_launch(void* const* d_in, const int* in_sizes, int n_in,
                              void* d_out, int out_size)
{
    const float* coords = (const float*)d_in[0];
    const float* ow1    = (const float*)d_in[1];
    const float* ob1    = (const float*)d_in[2];
    const float* ow2    = (const float*)d_in[3];
    const float* ob2    = (const float*)d_in[4];
    const float* w0     = (const float*)d_in[5];
    const float* b0     = (const float*)d_in[6];
    const float* wh     = (const float*)d_in[7];
    const float* bh     = (const float*)d_in[8];
    const float* wf     = (const float*)d_in[9];
    const float* bf     = (const float*)d_in[10];
    float* out = (float*)d_out;

    int n = in_sizes[0] / 4;
    int grid = n / MTILE;
    size_t smem_bytes = (size_t)SMEM_FLOATS * sizeof(float);   // ~98.25 KB

    cudaFuncSetAttribute(siren_fused_kernel,
                         cudaFuncAttributeMaxDynamicSharedMemorySize,
                         (int)smem_bytes);
    siren_fused_kernel<<<grid, THREADS, smem_bytes>>>(
        coords, ow1, ob1, ow2, ob2, w0, b0, wh, bh, wf, bf, out);
}

// round 4
// speedup vs baseline: 1.0060x; 1.0060x over previous
#include <cuda_runtime.h>
#include <cstdint>

#define HIDDEN   256
#define NHL      4
#define MTILE    64
#define KS       16
#define NSLAB    16         // HIDDEN / KS
#define THREADS  256
#define NSLABS_TOTAL (NHL * NSLAB)

// smem (floats): xa[64*256] wbuf[2*16*256] omg[64] cs[256] wfs[256]  ~= 98.25 KB
#define SMEM_FLOATS (MTILE*HIDDEN + 2*KS*HIDDEN + MTILE + MTILE*4 + HIDDEN)

__device__ __forceinline__ void cp_async16(float* dst, const float4* src) {
    uint32_t s = (uint32_t)__cvta_generic_to_shared(dst);
    asm volatile("cp.async.cg.shared.global [%0], [%1], 16;\n" :: "r"(s), "l"(src));
}
__device__ __forceinline__ void cp_commit() { asm volatile("cp.async.commit_group;\n" ::); }
template<int W> __device__ __forceinline__ void cp_wait() {
    asm volatile("cp.async.wait_group %0;\n" :: "n"(W));
}

// ---- packed fp32x2 helpers (FFMA2 path) ----
__device__ __forceinline__ void fma2(uint64_t& d, uint64_t a, uint64_t b) {
    asm volatile("fma.rn.f32x2 %0, %1, %2, %0;" : "+l"(d) : "l"(a), "l"(b));
}
__device__ __forceinline__ uint64_t fma2v(uint64_t a, uint64_t b, uint64_t c) {
    uint64_t d; asm("fma.rn.f32x2 %0, %1, %2, %3;" : "=l"(d) : "l"(a), "l"(b), "l"(c)); return d;
}
__device__ __forceinline__ uint64_t mul2(uint64_t a, uint64_t b) {
    uint64_t d; asm("mul.rn.f32x2 %0, %1, %2;" : "=l"(d) : "l"(a), "l"(b)); return d;
}
__device__ __forceinline__ uint64_t add2(uint64_t a, uint64_t b) {
    uint64_t d; asm("add.rn.f32x2 %0, %1, %2;" : "=l"(d) : "l"(a), "l"(b)); return d;
}
__device__ __forceinline__ uint64_t dup2(float x) {
    uint64_t d; asm("mov.b64 %0, {%1, %1};" : "=l"(d) : "f"(x)); return d;
}
__device__ __forceinline__ uint64_t pack2(float lo, float hi) {
    uint64_t d; asm("mov.b64 %0, {%1, %2};" : "=l"(d) : "f"(lo), "f"(hi)); return d;
}
// non-volatile so the compiler can CSE/hoist packed constants
__device__ __forceinline__ uint64_t c2(float x) {
    uint64_t d; asm("mov.b64 %0, {%1, %1};" : "=l"(d) : "f"(x)); return d;
}

// packed sine: magic-number range reduction to [-pi,pi] + degree-15 odd poly.
// worst-case abs err ~8e-7 at |r|=pi; no MUFU.
__device__ __forceinline__ uint64_t sin2(uint64_t x) {
    uint64_t n = add2(fma2v(x, c2(0.15915494309189535f), c2(12582912.0f)),
                      c2(-12582912.0f));
    uint64_t r = fma2v(n, c2(-6.2831854820251465f), x);
    r = fma2v(n, c2(1.7484555e-7f), r);
    uint64_t r2 = mul2(r, r);
    uint64_t p = c2(-7.6471637e-13f);
    p = fma2v(p, r2, c2(1.6059044e-10f));
    p = fma2v(p, r2, c2(-2.5052108e-8f));
    p = fma2v(p, r2, c2(2.7557319e-6f));
    p = fma2v(p, r2, c2(-1.9841270e-4f));
    p = fma2v(p, r2, c2(8.3333333e-3f));
    p = fma2v(p, r2, c2(-1.6666667e-1f));
    p = fma2v(p, r2, c2(1.0f));
    return mul2(p, r);
}

__device__ __forceinline__ float4 ldg4(const float* p) {
    return __ldg(reinterpret_cast<const float4*>(p));
}

// stream weight slab g (64 slabs of 16x256) into wbuf[g&1]
__device__ __forceinline__ void issue_slab(const float* __restrict__ wh,
                                           float* wbuf, int g, int tid) {
    const float4* src = reinterpret_cast<const float4*>(wh + (size_t)g * KS * HIDDEN) + tid;
    float* dst = wbuf + (g & 1) * (KS * HIDDEN) + tid * 4;
    #pragma unroll
    for (int r = 0; r < (KS * HIDDEN / 4) / THREADS; r++)
        cp_async16(dst + r * THREADS * 4, src + r * THREADS);
    cp_commit();
}

__global__ void __launch_bounds__(THREADS, 2)
siren_fused_kernel(const float* __restrict__ coords,
                   const float* __restrict__ ow1, const float* __restrict__ ob1,
                   const float* __restrict__ ow2, const float* __restrict__ ob2,
                   const float* __restrict__ w0,  const float* __restrict__ b0,
                   const float* __restrict__ wh,  const float* __restrict__ bh,
                   const float* __restrict__ wf,  const float* __restrict__ bf,
                   float* __restrict__ out)
{
    extern __shared__ float smem[];
    float* xa   = smem;                       // [64][256] single buffer (per-warp rows)
    float* wbuf = xa + MTILE * HIDDEN;        // [2][KS*HIDDEN]
    float* omg  = wbuf + 2 * KS * HIDDEN;     // [64]
    float* cs   = omg + MTILE;                // [64][4]
    float* wfs  = cs + MTILE * 4;             // [256]

    const int tid = threadIdx.x;
    const int mt  = tid >> 5;
    const int nt  = tid & 31;
    const int m0  = mt * 8;
    const int cA  = nt * 4;
    const int cB  = 128 + nt * 4;
    const long base = (long)blockIdx.x * MTILE;

    issue_slab(wh, wbuf, 0, tid);

    cs[tid]  = coords[base * 4 + tid];
    wfs[tid] = wf[tid];
    __syncthreads();

    // ---- omega predictor (threads 0..63): 1 expf per point, negligible MUFU ----
    if (tid < MTILE) {
        float c0 = cs[tid * 4 + 0], c1 = cs[tid * 4 + 1];
        float c2v = cs[tid * 4 + 2], c3 = cs[tid * 4 + 3];
        float s = __ldg(ob2);
        #pragma unroll 4
        for (int j = 0; j < 64; j++) {
            float h = __ldg(&ow1[j]) * c0;
            h = fmaf(__ldg(&ow1[64  + j]), c1, h);
            h = fmaf(__ldg(&ow1[128 + j]), c2v, h);
            h = fmaf(__ldg(&ow1[192 + j]), c3, h);
            h += __ldg(&ob1[j]);
            h = fmaxf(h, 0.0f);
            s = fmaf(h, __ldg(&ow2[j]), s);
        }
        float sig = 1.0f / (1.0f + __expf(-s));
        omg[tid] = 10.0f + 90.0f * sig;
    }
    __syncthreads();

    // ---- SIREN layer 0: x = sin(omega * (coords @ w0 + b0)), K=4 ----
    {
        float accA[8][4], accB[8][4];
        #pragma unroll
        for (int i = 0; i < 8; i++)
            #pragma unroll
            for (int j = 0; j < 4; j++) { accA[i][j] = 0.0f; accB[i][j] = 0.0f; }
        #pragma unroll
        for (int k = 0; k < 4; k++) {
            float4 bA = ldg4(&w0[k * HIDDEN + cA]);
            float4 bB = ldg4(&w0[k * HIDDEN + cB]);
            #pragma unroll
            for (int i = 0; i < 8; i++) {
                float a = cs[(m0 + i) * 4 + k];
                accA[i][0] = fmaf(a, bA.x, accA[i][0]);
                accA[i][1] = fmaf(a, bA.y, accA[i][1]);
                accA[i][2] = fmaf(a, bA.z, accA[i][2]);
                accA[i][3] = fmaf(a, bA.w, accA[i][3]);
                accB[i][0] = fmaf(a, bB.x, accB[i][0]);
                accB[i][1] = fmaf(a, bB.y, accB[i][1]);
                accB[i][2] = fmaf(a, bB.z, accB[i][2]);
                accB[i][3] = fmaf(a, bB.w, accB[i][3]);
            }
        }
        ulonglong2 biA = __ldg(reinterpret_cast<const ulonglong2*>(&b0[cA]));
        ulonglong2 biB = __ldg(reinterpret_cast<const ulonglong2*>(&b0[cB]));
        #pragma unroll
        for (int i = 0; i < 8; i++) {
            uint64_t om2 = dup2(omg[m0 + i]);
            ulonglong2 vA, vB;
            vA.x = sin2(mul2(om2, add2(pack2(accA[i][0], accA[i][1]), biA.x)));
            vA.y = sin2(mul2(om2, add2(pack2(accA[i][2], accA[i][3]), biA.y)));
            vB.x = sin2(mul2(om2, add2(pack2(accB[i][0], accB[i][1]), biB.x)));
            vB.y = sin2(mul2(om2, add2(pack2(accB[i][2], accB[i][3]), biB.y)));
            *reinterpret_cast<ulonglong2*>(&xa[(m0 + i) * HIDDEN + cA]) = vA;
            *reinterpret_cast<ulonglong2*>(&xa[(m0 + i) * HIDDEN + cB]) = vB;
        }
    }
    __syncwarp();

    // ---- 4 hidden layers, in-place update of xa, FFMA2 mainloop ----
    #pragma unroll 1
    for (int l = 0; l < NHL; l++) {
        uint64_t accA[8][2], accB[8][2];
        #pragma unroll
        for (int i = 0; i < 8; i++) {
            accA[i][0] = 0ull; accA[i][1] = 0ull;
            accB[i][0] = 0ull; accB[i][1] = 0ull;
        }

        #pragma unroll 1
        for (int s = 0; s < NSLAB; s++) {
            int g = l * NSLAB + s;
            if (g + 1 < NSLABS_TOTAL) {
                issue_slab(wh, wbuf, g + 1, tid);
                cp_wait<1>();
            } else {
                cp_wait<0>();
            }
            __syncthreads();
            const float* wb = wbuf + (g & 1) * (KS * HIDDEN);
            const float* xk = &xa[m0 * HIDDEN + s * KS];

            #pragma unroll 2
            for (int kp = 0; kp < KS / 2; kp++) {
                float2 a[8];
                #pragma unroll
                for (int i = 0; i < 8; i++)
                    a[i] = *reinterpret_cast<const float2*>(xk + i * HIDDEN + kp * 2);
                #pragma unroll
                for (int kk = 0; kk < 2; kk++) {
                    ulonglong2 bA = *reinterpret_cast<const ulonglong2*>(&wb[(kp * 2 + kk) * HIDDEN + cA]);
                    ulonglong2 bB = *reinterpret_cast<const ulonglong2*>(&wb[(kp * 2 + kk) * HIDDEN + cB]);
                    #pragma unroll
                    for (int i = 0; i < 8; i++) {
                        uint64_t ad = dup2(kk ? a[i].y : a[i].x);
                        fma2(accA[i][0], ad, bA.x);
                        fma2(accA[i][1], ad, bA.y);
                        fma2(accB[i][0], ad, bB.x);
                        fma2(accB[i][1], ad, bB.y);
                    }
                }
            }
            __syncthreads();
        }

        ulonglong2 bhA = __ldg(reinterpret_cast<const ulonglong2*>(&bh[l * HIDDEN + cA]));
        ulonglong2 bhB = __ldg(reinterpret_cast<const ulonglong2*>(&bh[l * HIDDEN + cB]));
        __syncwarp();
        #pragma unroll
        for (int i = 0; i < 8; i++) {
            uint64_t om2 = dup2(omg[m0 + i]);
            ulonglong2 vA, vB;
            vA.x = sin2(mul2(om2, add2(accA[i][0], bhA.x)));
            vA.y = sin2(mul2(om2, add2(accA[i][1], bhA.y)));
            vB.x = sin2(mul2(om2, add2(accB[i][0], bhB.x)));
            vB.y = sin2(mul2(om2, add2(accB[i][1], bhB.y)));
            *reinterpret_cast<ulonglong2*>(&xa[(m0 + i) * HIDDEN + cA]) = vA;
            *reinterpret_cast<ulonglong2*>(&xa[(m0 + i) * HIDDEN + cB]) = vB;
        }
        __syncwarp();
    }

    // ---- head: out[m] = x[m] @ wf + bf (one warp per 8 points) ----
    {
        const int w = tid >> 5, lane = tid & 31;
        const float bfv = __ldg(bf);
        const float4* wr = reinterpret_cast<const float4*>(&wfs[lane * 8]);
        float4 w1 = wr[0], w2 = wr[1];
        #pragma unroll
        for (int p = 0; p < 8; p++) {
            int m = w * 8 + p;
            const float4* xr = reinterpret_cast<const float4*>(&xa[m * HIDDEN + lane * 8]);
            float4 x1 = xr[0], x2 = xr[1];
            float par = x1.x * w1.x + x1.y * w1.y + x1.z * w1.z + x1.w * w1.w
                      + x2.x * w2.x + x2.y * w2.y + x2.z * w2.z + x2.w * w2.w;
            #pragma unroll
            for (int off = 16; off > 0; off >>= 1)
                par += __shfl_xor_sync(0xffffffff, par, off);
            if (lane == 0) out[base + m] = par + bfv;
        }
    }
}

extern "C" void kernel_launch(void* const* d_in, const int* in_sizes, int n_in,
                              void* d_out, int out_size)
{
    const float* coords = (const float*)d_in[0];
    const float* ow1    = (const float*)d_in[1];
    const float* ob1    = (const float*)d_in[2];
    const float* ow2    = (const float*)d_in[3];
    const float* ob2    = (const float*)d_in[4];
    const float* w0     = (const float*)d_in[5];
    const float* b0     = (const float*)d_in[6];
    const float* wh     = (const float*)d_in[7];
    const float* bh     = (const float*)d_in[8];
    const float* wf     = (const float*)d_in[9];
    const float* bf     = (const float*)d_in[10];
    float* out = (float*)d_out;

    int n = in_sizes[0] / 4;
    int grid = n / MTILE;
    size_t smem_bytes = (size_t)SMEM_FLOATS * sizeof(float);

    cudaFuncSetAttribute(siren_fused_kernel,
                         cudaFuncAttributeMaxDynamicSharedMemorySize,
                         (int)smem_bytes);
    siren_fused_kernel<<<grid, THREADS, smem_bytes>>>(
        coords, ow1, ob1, ow2, ob2, w0, b0, wh, bh, wf, bf, out);
}